// round 9
// baseline (speedup 1.0000x reference)
#include <cuda_runtime.h>

// Problem constants (B=8192, L=2048, T=1024)
#define NB 8192
#define NT 1024
#define THREADS 256
#define NWARPS (THREADS / 32)

__device__ double g_sum = 0.0;          // zeroed by last block each launch
__device__ unsigned int g_count = 0;    // zeroed by last block each launch

// Block-per-row. Thread t owns points 4t..4t+3 (8 contiguous pred floats).
// Error partials (e2, e1x, e1y) are computed relative to the thread's own
// chunk start, so they don't depend on the prefix scan; the global offset is
// folded in afterwards with 6 FMAs:  err = e2 + 2*O.e1 + 4*|O|^2.
__global__ __launch_bounds__(THREADS) void traj_loss_fused(
    const float* __restrict__ pred,
    const float* __restrict__ pos_true,
    float* __restrict__ out)
{
    const int b    = blockIdx.x;
    const int tid  = threadIdx.x;
    const int lane = tid & 31;
    const int warp = tid >> 5;

    // --- loads: all four issued up-front, independent (MLP) ---
    const float4* pv = (const float4*)(pred + (size_t)b * (2 * NT));
    float4 a = pv[2 * tid];       // x0 y0 x1 y1
    float4 c = pv[2 * tid + 1];   // x2 y2 x3 y3

    const float* tp = pos_true + (size_t)b * (2 * NT);
    float4 tx = ((const float4*)tp)[tid];        // unit-stride
    float4 ty = ((const float4*)(tp + NT))[tid]; // unit-stride

    // --- thread-local prefix positions (relative to own chunk start) ---
    float p1x = a.x,       p1y = a.y;
    float p2x = p1x + a.z, p2y = p1y + a.w;
    float p3x = p2x + c.x, p3y = p2y + c.y;
    float p4x = p3x + c.z, p4y = p3y + c.w;   // == thread delta totals (lx, ly)

    // --- error partials, independent of the scan ---
    float dx, dy;
    float e2 = 0.0f, e1x = 0.0f, e1y = 0.0f;
    dx = p1x - tx.x; dy = p1y - ty.x; e2 += dx * dx + dy * dy; e1x += dx; e1y += dy;
    dx = p2x - tx.y; dy = p2y - ty.y; e2 += dx * dx + dy * dy; e1x += dx; e1y += dy;
    dx = p3x - tx.z; dy = p3y - ty.z; e2 += dx * dx + dy * dy; e1x += dx; e1y += dy;
    dx = p4x - tx.w; dy = p4y - ty.w; e2 += dx * dx + dy * dy; e1x += dx; e1y += dy;

    // --- warp inclusive scan of thread delta totals (runs concurrently with
    //     the FMA chain above from the scheduler's perspective) ---
    const float lx = p4x, ly = p4y;
    float sx = lx, sy = ly;
    #pragma unroll
    for (int d = 1; d < 32; d <<= 1) {
        float ux = __shfl_up_sync(0xffffffffu, sx, d);
        float uy = __shfl_up_sync(0xffffffffu, sy, d);
        if (lane >= d) { sx += ux; sy += uy; }
    }

    __shared__ float wx[NWARPS], wy[NWARPS];
    if (lane == 31) { wx[warp] = sx; wy[warp] = sy; }
    __syncthreads();

    // exclusive offset for this thread = (inclusive - local) + prior warp totals
    float ox = sx - lx, oy = sy - ly;
    #pragma unroll
    for (int w = 0; w < NWARPS - 1; w++) {
        float addx = wx[w], addy = wy[w];
        if (w < warp) { ox += addx; oy += addy; }
    }

    // --- fold offset into error: 6 FMAs ---
    float err = e2 + 2.0f * (ox * e1x + oy * e1y) + 4.0f * (ox * ox + oy * oy);

    // --- block reduce: float shuffles, double only at block partial ---
    #pragma unroll
    for (int d = 16; d > 0; d >>= 1)
        err += __shfl_down_sync(0xffffffffu, err, d);

    __shared__ float wsum[NWARPS];
    if (lane == 0) wsum[warp] = err;
    __syncthreads();

    if (warp == 0 && lane == 0) {
        double v = 0.0;
        #pragma unroll
        for (int w = 0; w < NWARPS; w++) v += (double)wsum[w];

        atomicAdd(&g_sum, v);
        __threadfence();
        unsigned int old = atomicAdd(&g_count, 1u);
        if (old == NB - 1) {
            // last block: read-and-zero accumulator, reset counter (graph-replay safe)
            unsigned long long bits = atomicExch((unsigned long long*)&g_sum, 0ULL);
            g_count = 0;
            out[0] = (float)__longlong_as_double(bits);
        }
    }
}

extern "C" void kernel_launch(void* const* d_in, const int* in_sizes, int n_in,
                              void* d_out, int out_size)
{
    const float* pred     = (const float*)d_in[0];  // traj_pred
    // d_in[1] = traj_du_true — unused by the reference; never read.
    const float* pos_true = (const float*)d_in[2];  // traj_pos_true

    traj_loss_fused<<<NB, THREADS>>>(pred, pos_true, (float*)d_out);
}